// round 8
// baseline (speedup 1.0000x reference)
#include <cuda_runtime.h>
#include <cuda_fp16.h>
#include <cstdint>

// Problem dims (fixed)
#define M_TOT 16384   // B*L
#define N_TOT 2048    // 2*D
#define K_TOT 1024    // D
#define BATCH 4
#define SEQL  4096
#define DIM   1024
#define NCHUNK 64
#define CHUNK  64     // SEQL / NCHUNK

// ---------------- scratch ----------------
__device__ __align__(256) __half g_hgh[(size_t)M_TOT * N_TOT];   // 67MB GEMM out (fp16)
__device__ __align__(256) __half g_xh[(size_t)M_TOT * K_TOT];
__device__ __align__(256) __half g_wh[(size_t)N_TOT * K_TOT];
__device__ float g_sumP[BATCH * NCHUNK * DIM];
__device__ float g_sumH[BATCH * NCHUNK * DIM];
__device__ float g_hstart[BATCH * NCHUNK * DIM];

// ---------------- PTX helpers (base sm_100 legal only) ----------------
__device__ __forceinline__ uint32_t smem_u32(const void* p) {
    uint32_t a;
    asm("{ .reg .u64 t; cvta.to.shared.u64 t, %1; cvt.u32.u64 %0, t; }"
        : "=r"(a) : "l"(p));
    return a;
}
__device__ __forceinline__ void cp16(uint32_t dst, const void* src) {
    asm volatile("cp.async.cg.shared.global [%0], [%1], 16;" :: "r"(dst), "l"(src));
}
#define CP_COMMIT() asm volatile("cp.async.commit_group;" ::: "memory")
#define CP_WAIT0()  asm volatile("cp.async.wait_group 0;" ::: "memory")
#define CP_WAIT1()  asm volatile("cp.async.wait_group 1;" ::: "memory")

#define LDSM4(r0, r1, r2, r3, a) \
    asm volatile("ldmatrix.sync.aligned.m8n8.x4.shared.b16 {%0,%1,%2,%3}, [%4];" \
                 : "=r"(r0), "=r"(r1), "=r"(r2), "=r"(r3) : "r"(a))

#define MMA16816(c, a, b) \
    asm volatile( \
        "mma.sync.aligned.m16n8k16.row.col.f32.f16.f16.f32 " \
        "{%0,%1,%2,%3}, {%4,%5,%6,%7}, {%8,%9}, {%0,%1,%2,%3};" \
        : "+f"((c)[0]), "+f"((c)[1]), "+f"((c)[2]), "+f"((c)[3]) \
        : "r"((a)[0]), "r"((a)[1]), "r"((a)[2]), "r"((a)[3]), \
          "r"((b)[0]), "r"((b)[1]))

// ---------------- f32 -> f16 convert ----------------
__global__ void conv_kernel(const float* __restrict__ src,
                            __half* __restrict__ dst, int n4) {
    int i = blockIdx.x * blockDim.x + threadIdx.x;
    if (i >= n4) return;
    float4 v = reinterpret_cast<const float4*>(src)[i];
    reinterpret_cast<__half2*>(dst)[2 * i] =
        __halves2half2(__float2half_rn(v.x), __float2half_rn(v.y));
    reinterpret_cast<__half2*>(dst)[2 * i + 1] =
        __halves2half2(__float2half_rn(v.z), __float2half_rn(v.w));
}

// ------- mma.sync GEMM: 128M x 128N per CTA, BK=64, 3 stages, 2 CTA/SM ----
// Smem row = 64 halves = 128B; 16B chunks swizzled: chunk ^= (row & 7)
#define OFF_A 0
#define OFF_B 16384
#define STAGE_BYTES 32768
#define NSTAGES 3
#define SMEM_DYN (NSTAGES * STAGE_BYTES)
#define NT (K_TOT / 64)   // 16

__device__ __forceinline__ void load_stage(uint32_t sbase, int buf, int kc,
                                           int bm, int bn, int tid) {
    uint32_t s = sbase + (uint32_t)buf * STAGE_BYTES;
#pragma unroll
    for (int i = 0; i < 4; i++) {      // A: 128 rows x 8 chunks = 1024
        int ch = tid + i * 256;
        int row = ch >> 3, c = ch & 7;
        uint32_t off = (uint32_t)(row * 128) + (uint32_t)((c ^ (row & 7)) << 4);
        cp16(s + OFF_A + off, g_xh + (size_t)(bm + row) * K_TOT + kc + c * 8);
    }
#pragma unroll
    for (int i = 0; i < 4; i++) {      // B: 128 rows x 8 chunks = 1024
        int ch = tid + i * 256;
        int row = ch >> 3, c = ch & 7;
        uint32_t off = (uint32_t)(row * 128) + (uint32_t)((c ^ (row & 7)) << 4);
        cp16(s + OFF_B + off, g_wh + (size_t)(bn + row) * K_TOT + kc + c * 8);
    }
    CP_COMMIT();
}

__global__ __launch_bounds__(256, 2) void gemm_mma_kernel() {
    extern __shared__ __align__(1024) char dyn_smem[];
    const int tid = threadIdx.x;
    const int wid = tid >> 5;
    const int lane = tid & 31;
    const int bm = blockIdx.y * 128;
    const int bn = blockIdx.x * 128;
    const int warp_m = wid & 3;     // 4 warps along M (32 rows each)
    const int warp_n = wid >> 2;    // 2 warps along N (64 cols each)

    uint32_t sbase = smem_u32(dyn_smem);

    const int j4 = lane >> 3;
    const int rin = lane & 7;
    // A x4: m0,m1 = rows 0-7/8-15 @k0; m2,m3 = same @k1
    const int a_moff = (j4 & 1) * 8 + rin;
    const int a_kj = j4 >> 1;
    int aoff[2], asw[2];
#pragma unroll
    for (int i = 0; i < 2; i++) {
        int r = warp_m * 32 + i * 16 + a_moff;
        aoff[i] = r * 128;
        asw[i] = r & 7;
    }
    // B x4: m0,m1 = n rows jj*16 + (rin) @k0/k1; m2,m3 = +8 @k0/k1
    const int b_noff = (j4 >> 1) * 8 + rin;
    const int b_kj = j4 & 1;
    int boff[4], bsw[4];
#pragma unroll
    for (int jj = 0; jj < 4; jj++) {
        int r = warp_n * 64 + jj * 16 + b_noff;
        boff[jj] = r * 128;
        bsw[jj] = r & 7;
    }

    float acc[2][8][4];
#pragma unroll
    for (int i = 0; i < 2; i++)
#pragma unroll
        for (int j = 0; j < 8; j++)
#pragma unroll
            for (int q = 0; q < 4; q++) acc[i][j][q] = 0.f;

    load_stage(sbase, 0, 0, bm, bn, tid);
    load_stage(sbase, 1, 64, bm, bn, tid);

#pragma unroll 1
    for (int t = 0; t < NT; t++) {
        if (t < NT - 1) { CP_WAIT1(); } else { CP_WAIT0(); }
        __syncthreads();

        if (t + 2 < NT) {
            int buf = (t + 2) % 3;
            load_stage(sbase, buf, (t + 2) * 64, bm, bn, tid);
        }

        const uint32_t s = sbase + (uint32_t)(t % 3) * STAGE_BYTES;
        const uint32_t sA = s + OFF_A, sB = s + OFF_B;

#pragma unroll
        for (int ks = 0; ks < 4; ks++) {
            uint32_t Af[2][4], Bf[8][2];
#pragma unroll
            for (int i = 0; i < 2; i++) {
                uint32_t co = (uint32_t)(((ks * 2 + a_kj) ^ asw[i]) << 4);
                LDSM4(Af[i][0], Af[i][1], Af[i][2], Af[i][3], sA + aoff[i] + co);
            }
#pragma unroll
            for (int jj = 0; jj < 4; jj++) {
                uint32_t co = (uint32_t)(((ks * 2 + b_kj) ^ bsw[jj]) << 4);
                LDSM4(Bf[2 * jj][0], Bf[2 * jj][1], Bf[2 * jj + 1][0],
                      Bf[2 * jj + 1][1], sB + boff[jj] + co);
            }
#pragma unroll
            for (int i = 0; i < 2; i++)
#pragma unroll
                for (int j = 0; j < 8; j++) MMA16816(acc[i][j], Af[i], Bf[j]);
        }
        __syncthreads();
    }

    // epilogue: fp16 store
    const int erow = lane >> 2;
    const int ecol = (lane & 3) * 2;
    __half* hgh = g_hgh;
#pragma unroll
    for (int i = 0; i < 2; i++) {
        const int m0 = bm + warp_m * 32 + i * 16 + erow;
#pragma unroll
        for (int j = 0; j < 8; j++) {
            const int n0 = bn + warp_n * 64 + j * 8 + ecol;
            *reinterpret_cast<__half2*>(hgh + (size_t)m0 * N_TOT + n0) =
                __halves2half2(__float2half_rn(acc[i][j][0]),
                               __float2half_rn(acc[i][j][1]));
            *reinterpret_cast<__half2*>(hgh + (size_t)(m0 + 8) * N_TOT + n0) =
                __halves2half2(__float2half_rn(acc[i][j][2]),
                               __float2half_rn(acc[i][j][3]));
        }
    }
}

// ---------------- scan ----------------
__device__ __forceinline__ void scan_terms(float hid, float gat, float& cc,
                                           float& zg) {
    float e = __expf(-gat);
    float z = __fdividef(1.f, 1.f + e);
    cc = e * z;
    float eh = __expf(-fabsf(hid));
    float sg = __fdividef(eh, 1.f + eh);
    float g = (hid >= 0.f) ? (hid + 0.5f) : sg;
    zg = z * g;
}

// warp covers 64 channels: d = dg*64 + lane*2 (2 channels/thread via half2)
__global__ void scan_phase1() {
    const int gw = (blockIdx.x * blockDim.x + threadIdx.x) >> 5;   // 0..4095
    const int lane = threadIdx.x & 31;
    const int chunk = gw & (NCHUNK - 1);          // 0..63
    const int dg = (gw >> 6) & 15;                // 0..15
    const int b = gw >> 10;                       // 0..3
    const int d = dg * 64 + lane * 2;

    const __half* __restrict__ hg = g_hgh;
    size_t base = ((size_t)(b * SEQL + chunk * CHUNK)) * N_TOT + d;
    float h0 = 0.f, h1 = 0.f, p0 = 1.f, p1 = 1.f;
#pragma unroll 8
    for (int l = 0; l < CHUNK; l++) {
        float2 hid = __half22float2(
            *reinterpret_cast<const __half2*>(hg + base + (size_t)l * N_TOT));
        float2 gat = __half22float2(
            *reinterpret_cast<const __half2*>(hg + base + (size_t)l * N_TOT + DIM));
        float cc, zg;
        scan_terms(hid.x, gat.x, cc, zg);
        h0 = cc * h0 + zg; p0 *= cc;
        scan_terms(hid.y, gat.y, cc, zg);
        h1 = cc * h1 + zg; p1 *= cc;
    }
    const int sidx = (b * NCHUNK + chunk) * DIM + d;
    *reinterpret_cast<float2*>(g_sumH + sidx) = make_float2(h0, h1);
    *reinterpret_cast<float2*>(g_sumP + sidx) = make_float2(p0, p1);
}

__global__ void scan_phase2() {
    const int idx = blockIdx.x * blockDim.x + threadIdx.x;   // 0..4095
    const int b = idx >> 10;
    const int d = idx & (DIM - 1);
    float carry = 0.f;
#pragma unroll
    for (int ch = 0; ch < NCHUNK; ch++) {
        const int s = (b * NCHUNK + ch) * DIM + d;
        g_hstart[s] = carry;
        carry = g_sumP[s] * carry + g_sumH[s];
    }
}

__global__ void scan_phase3(float* __restrict__ out) {
    const int gw = (blockIdx.x * blockDim.x + threadIdx.x) >> 5;
    const int lane = threadIdx.x & 31;
    const int chunk = gw & (NCHUNK - 1);
    const int dg = (gw >> 6) & 15;
    const int b = gw >> 10;
    const int d = dg * 64 + lane * 2;

    const __half* __restrict__ hg = g_hgh;
    size_t base = ((size_t)(b * SEQL + chunk * CHUNK)) * N_TOT + d;
    size_t obase = ((size_t)(b * SEQL + chunk * CHUNK)) * DIM + d;
    const int sidx = (b * NCHUNK + chunk) * DIM + d;
    float2 hs = *reinterpret_cast<float2*>(g_hstart + sidx);
    float h0 = hs.x, h1 = hs.y;
#pragma unroll 8
    for (int l = 0; l < CHUNK; l++) {
        float2 hid = __half22float2(
            *reinterpret_cast<const __half2*>(hg + base + (size_t)l * N_TOT));
        float2 gat = __half22float2(
            *reinterpret_cast<const __half2*>(hg + base + (size_t)l * N_TOT + DIM));
        float cc, zg;
        scan_terms(hid.x, gat.x, cc, zg);
        h0 = cc * h0 + zg;
        scan_terms(hid.y, gat.y, cc, zg);
        h1 = cc * h1 + zg;
        *reinterpret_cast<float2*>(out + obase + (size_t)l * DIM) =
            make_float2(h0, h1);
    }
}

// ---------------- launch ----------------
extern "C" void kernel_launch(void* const* d_in, const int* in_sizes, int n_in,
                              void* d_out, int out_size) {
    const float* x = (const float*)d_in[0];   // [4,4096,1024]
    const float* W = (const float*)d_in[1];   // [2048,1024]
    float* out = (float*)d_out;               // [4,4096,1024]

    cudaFuncSetAttribute(gemm_mma_kernel,
                         cudaFuncAttributeMaxDynamicSharedMemorySize, SMEM_DYN);

    __half *xh, *wh;
    cudaGetSymbolAddress((void**)&xh, g_xh);
    cudaGetSymbolAddress((void**)&wh, g_wh);
    conv_kernel<<<(M_TOT * K_TOT / 4 + 255) / 256, 256>>>(x, xh,
                                                          M_TOT * K_TOT / 4);
    conv_kernel<<<(N_TOT * K_TOT / 4 + 255) / 256, 256>>>(W, wh,
                                                          N_TOT * K_TOT / 4);

    dim3 ggrid(N_TOT / 128, M_TOT / 128);   // (16, 128)
    gemm_mma_kernel<<<ggrid, 256, SMEM_DYN>>>();

    scan_phase1<<<512, 256>>>();
    scan_phase2<<<16, 256>>>();
    scan_phase3<<<512, 256>>>(out);
}